// round 8
// baseline (speedup 1.0000x reference)
#include <cuda_runtime.h>
#include <math.h>

// B=8192 rows, N=2048 anchors/row. Warp-per-row, 128-thread CTAs.
// Inputs: anchors (B,N,2) f32, offsets (B,N,2) f32, confidences (B,N) f32,
//         ground_truth (B,2) f32.  Output: 3 f32 (total, ce, huber).

#define B_SZ 8192
#define N_SZ 2048
#define NT   128
#define NW   (NT / 32)
#define ROWS_PER_CTA NW
#define GRID (B_SZ / ROWS_PER_CTA)
#define DELTA 0.04f
#define LOG_CLAMP -100.0f

__device__ __align__(16) float g_ce[B_SZ];
__device__ __align__(16) float g_hu[B_SZ];
__device__ unsigned g_count = 0;

__device__ __forceinline__ float warp_sum(float v) {
#pragma unroll
    for (int o = 16; o; o >>= 1) v += __shfl_xor_sync(0xffffffffu, v, o);
    return v;
}
__device__ __forceinline__ float huber1(float x) {
    float ax = fabsf(x);
    return (ax <= DELTA) ? 0.5f * x * x : DELTA * (ax - 0.5f * DELTA);
}

// argmin key: (float_bits(d) << 32) | idx — nonneg float bit order == value
// order, min() gives exact first-index tie-break.
__device__ __forceinline__ unsigned long long
amin2(const float4& a, int vi, float gx, float gy) {
    float dx0 = a.x - gx, dy0 = a.y - gy;
    float dx1 = a.z - gx, dy1 = a.w - gy;
    float d0 = fmaf(dx0, dx0, dy0 * dy0);
    float d1 = fmaf(dx1, dx1, dy1 * dy1);
    unsigned long long k0 = ((unsigned long long)__float_as_uint(d0) << 32) | (unsigned)(2 * vi);
    unsigned long long k1 = ((unsigned long long)__float_as_uint(d1) << 32) | (unsigned)(2 * vi + 1);
    return min(k0, k1);
}

__global__ __launch_bounds__(NT, 12) void fused_kernel(
    const float* __restrict__ anchors,
    const float* __restrict__ offsets,
    const float* __restrict__ conf,
    const float* __restrict__ gt,
    float* __restrict__ out)
{
    const int t    = threadIdx.x;
    const int warp = t >> 5, lane = t & 31;
    const int b    = blockIdx.x * ROWS_PER_CTA + warp;   // this warp's row

    __shared__ float s1[NW], s2[NW];
    __shared__ unsigned s_arrival;

    const float gx = __ldg(&gt[2 * b]);
    const float gy = __ldg(&gt[2 * b + 1]);

    const float4* c4 = reinterpret_cast<const float4*>(conf)    + (size_t)b * (N_SZ / 4) + lane;
    const float4* a4 = reinterpret_cast<const float4*>(anchors) + (size_t)b * (N_SZ / 2) + lane;

    float s1a = 0.f, s1b = 0.f, s2a = 0.f, s2b = 0.f;
    unsigned long long bk = 0xFFFFFFFFFFFFFFFFull;

    // 8 batches; each batch front-loads 6 float4 (2 conf + 4 anchors) before
    // computing, so ~6 LDGs are in flight per lane (MLP_eff >= 6).
#pragma unroll
    for (int jj = 0; jj < 8; jj++) {
        const int j = 2 * jj;
        float4 cf0 = __ldg(c4 + 32 * j);
        float4 cf1 = __ldg(c4 + 32 * (j + 1));
        float4 a0  = __ldg(a4 + 64 * j);
        float4 a1  = __ldg(a4 + 64 * j + 32);
        float4 a2  = __ldg(a4 + 64 * (j + 1));
        float4 a3  = __ldg(a4 + 64 * (j + 1) + 32);

        // softmax power sums: S1 = sum e, S2 = sum e^2
        {
            float e0 = __expf(cf0.x), e1 = __expf(cf0.y);
            float e2 = __expf(cf0.z), e3 = __expf(cf0.w);
            float f0 = __expf(cf1.x), f1 = __expf(cf1.y);
            float f2 = __expf(cf1.z), f3 = __expf(cf1.w);
            s1a += (e0 + e1) + (e2 + e3);
            s1b += (f0 + f1) + (f2 + f3);
            s2a = fmaf(e0, e0, fmaf(e1, e1, fmaf(e2, e2, fmaf(e3, e3, s2a))));
            s2b = fmaf(f0, f0, fmaf(f1, f1, fmaf(f2, f2, fmaf(f3, f3, s2b))));
        }

        // argmin of squared distance (sqrt monotone -> same argmin)
        bk = min(bk, amin2(a0, 64 * j + lane,            gx, gy));
        bk = min(bk, amin2(a1, 64 * j + 32 + lane,       gx, gy));
        bk = min(bk, amin2(a2, 64 * (j + 1) + lane,      gx, gy));
        bk = min(bk, amin2(a3, 64 * (j + 1) + 32 + lane, gx, gy));
    }

    // ---- warp-only reduction (no block barrier in hot path) ----
    float S1 = warp_sum(s1a + s1b);
    float S2 = warp_sum(s2a + s2b);
#pragma unroll
    for (int o = 16; o; o >>= 1) {
        unsigned long long ok = __shfl_xor_sync(0xffffffffu, bk, o);
        bk = min(bk, ok);
    }

    if (lane == 0) {
        const int biall = (int)(bk & 0xFFFFFFFFull);

        // sum_n log1p(-p_n) ~= -(1 + S2/(2 S1^2));  higher terms < 2e-6/row
        const float inv = 1.0f / S1;
        float polySum = -fmaf(0.5f * S2 * inv, inv, 1.0f);

        // exact terms at the argmin index
        float c_idx = __ldg(&conf[(size_t)b * N_SZ + biall]);
        float e_idx = __expf(c_idx);
        float u_idx = e_idx * inv;
        float lp    = fmaxf(__logf(u_idx), LOG_CLAMP);
        float l1    = fmaxf(log1pf(-u_idx), LOG_CLAMP);
        float ce    = -(lp + polySum - l1);

        // Huber on gathered closest anchor/offset
        const float* ap = anchors + (size_t)b * N_SZ * 2 + 2 * biall;
        const float* op = offsets + (size_t)b * N_SZ * 2 + 2 * biall;
        float ax = __ldg(&ap[0]), ay = __ldg(&ap[1]);
        float ox = __ldg(&op[0]), oy = __ldg(&op[1]);
        float hu = huber1(ox - (gx - ax)) + huber1(oy - (gy - ay));

        g_ce[b] = ce;
        g_hu[b] = hu;
        __threadfence();          // publish before this CTA signals arrival
    }

    __syncthreads();
    if (t == 0) {
        __threadfence();
        s_arrival = atomicAdd(&g_count, 1u);
    }
    __syncthreads();

    // ---- last CTA: deterministic fixed-order 8192 -> 3 reduction ----
    if (s_arrival == GRID - 1) {
        __threadfence();
        float ce = 0.f, hu = 0.f;
        const float4* ce4 = reinterpret_cast<const float4*>(g_ce);
        const float4* hu4 = reinterpret_cast<const float4*>(g_hu);
#pragma unroll
        for (int k = 0; k < 16; k++) {    // thread t owns [t*64, t*64+64)
            float4 v = ce4[t * 16 + k];
            ce += (v.x + v.y) + (v.z + v.w);
        }
#pragma unroll
        for (int k = 0; k < 16; k++) {
            float4 v = hu4[t * 16 + k];
            hu += (v.x + v.y) + (v.z + v.w);
        }
        ce = warp_sum(ce);
        hu = warp_sum(hu);
        if (lane == 0) { s1[warp] = ce; s2[warp] = hu; }
        __syncthreads();
        if (t == 0) {
            float cet = s1[0], hut = s2[0];
#pragma unroll
            for (int w = 1; w < NW; w++) { cet += s1[w]; hut += s2[w]; }
            out[0] = cet + hut;
            out[1] = cet;
            out[2] = hut;
            g_count = 0;          // reset for next graph replay
        }
    }
}

extern "C" void kernel_launch(void* const* d_in, const int* in_sizes, int n_in,
                              void* d_out, int out_size)
{
    const float* anchors = (const float*)d_in[0];
    const float* offsets = (const float*)d_in[1];
    const float* conf    = (const float*)d_in[2];
    const float* gt      = (const float*)d_in[3];
    float* out = (float*)d_out;

    fused_kernel<<<GRID, NT>>>(anchors, offsets, conf, gt, out);
}

// round 9
// speedup vs baseline: 1.3028x; 1.3028x over previous
#include <cuda_runtime.h>
#include <math.h>

// B=8192 rows, N=2048 anchors/row. Warp-per-row, 256-thread CTAs (R6 base),
// software-pipelined loads (prefetch next stage during current compute).
// Inputs: anchors (B,N,2) f32, offsets (B,N,2) f32, confidences (B,N) f32,
//         ground_truth (B,2) f32.  Output: 3 f32 (total, ce, huber).

#define B_SZ 8192
#define N_SZ 2048
#define NT   256
#define NW   (NT / 32)
#define ROWS_PER_CTA NW
#define GRID (B_SZ / ROWS_PER_CTA)
#define DELTA 0.04f
#define LOG_CLAMP -100.0f

__device__ __align__(16) float g_ce[B_SZ];
__device__ __align__(16) float g_hu[B_SZ];
__device__ unsigned g_count = 0;

__device__ __forceinline__ float warp_sum(float v) {
#pragma unroll
    for (int o = 16; o; o >>= 1) v += __shfl_xor_sync(0xffffffffu, v, o);
    return v;
}
__device__ __forceinline__ float huber1(float x) {
    float ax = fabsf(x);
    return (ax <= DELTA) ? 0.5f * x * x : DELTA * (ax - 0.5f * DELTA);
}

// argmin key: (float_bits(d) << 32) | idx — nonneg float bit order == value
// order, min() gives exact first-index tie-break.
__device__ __forceinline__ unsigned long long
amin2(const float4& a, int vi, float gx, float gy) {
    float dx0 = a.x - gx, dy0 = a.y - gy;
    float dx1 = a.z - gx, dy1 = a.w - gy;
    float d0 = fmaf(dx0, dx0, dy0 * dy0);
    float d1 = fmaf(dx1, dx1, dy1 * dy1);
    unsigned long long k0 = ((unsigned long long)__float_as_uint(d0) << 32) | (unsigned)(2 * vi);
    unsigned long long k1 = ((unsigned long long)__float_as_uint(d1) << 32) | (unsigned)(2 * vi + 1);
    return min(k0, k1);
}

__global__ __launch_bounds__(NT, 7) void fused_kernel(
    const float* __restrict__ anchors,
    const float* __restrict__ offsets,
    const float* __restrict__ conf,
    const float* __restrict__ gt,
    float* __restrict__ out)
{
    const int t    = threadIdx.x;
    const int warp = t >> 5, lane = t & 31;
    const int b    = blockIdx.x * ROWS_PER_CTA + warp;   // this warp's row

    __shared__ float s1[NW], s2[NW];
    __shared__ unsigned s_arrival;

    const float gx = __ldg(&gt[2 * b]);
    const float gy = __ldg(&gt[2 * b + 1]);

    const float4* c4 = reinterpret_cast<const float4*>(conf)    + (size_t)b * (N_SZ / 4) + lane;
    const float4* a4 = reinterpret_cast<const float4*>(anchors) + (size_t)b * (N_SZ / 2) + lane;

    float s1a = 0.f, s1b = 0.f, s2a = 0.f, s2b = 0.f;
    unsigned long long bk = 0xFFFFFFFFFFFFFFFFull;

    // ---- software-pipelined main loop: 16 stages of (1 conf4 + 2 anchor4).
    // Stage j+1's loads are issued BEFORE stage j's compute, so ~3 LDG.128
    // stay in flight per lane during every compute phase.
    float4 cf = __ldg(c4);
    float4 a0 = __ldg(a4);
    float4 a1 = __ldg(a4 + 32);

#pragma unroll
    for (int j = 0; j < 16; j++) {
        float4 cfn, a0n, a1n;
        if (j < 15) {
            cfn = __ldg(c4 + 32 * (j + 1));
            a0n = __ldg(a4 + 64 * (j + 1));
            a1n = __ldg(a4 + 64 * (j + 1) + 32);
        }

        // softmax power sums: S1 = sum e, S2 = sum e^2
        float e0 = __expf(cf.x), e1 = __expf(cf.y);
        float e2 = __expf(cf.z), e3 = __expf(cf.w);
        s1a += e0 + e1;
        s1b += e2 + e3;
        s2a = fmaf(e0, e0, fmaf(e1, e1, s2a));
        s2b = fmaf(e2, e2, fmaf(e3, e3, s2b));

        // argmin of squared distance (sqrt monotone -> same argmin)
        bk = min(bk, amin2(a0, 64 * j + lane,      gx, gy));
        bk = min(bk, amin2(a1, 64 * j + 32 + lane, gx, gy));

        cf = cfn; a0 = a0n; a1 = a1n;
    }

    // ---- warp-only reduction (no block barrier in hot path) ----
    float S1 = warp_sum(s1a + s1b);
    float S2 = warp_sum(s2a + s2b);
#pragma unroll
    for (int o = 16; o; o >>= 1) {
        unsigned long long ok = __shfl_xor_sync(0xffffffffu, bk, o);
        bk = min(bk, ok);
    }

    if (lane == 0) {
        const int biall = (int)(bk & 0xFFFFFFFFull);

        // sum_n log1p(-p_n) ~= -(1 + S2/(2 S1^2));  higher terms < 2e-6/row
        const float inv = 1.0f / S1;
        float polySum = -fmaf(0.5f * S2 * inv, inv, 1.0f);

        // exact terms at the argmin index
        float c_idx = __ldg(&conf[(size_t)b * N_SZ + biall]);
        float e_idx = __expf(c_idx);
        float u_idx = e_idx * inv;
        float lp    = fmaxf(__logf(u_idx), LOG_CLAMP);
        float l1    = fmaxf(log1pf(-u_idx), LOG_CLAMP);
        float ce    = -(lp + polySum - l1);

        // Huber on gathered closest anchor/offset
        const float* ap = anchors + (size_t)b * N_SZ * 2 + 2 * biall;
        const float* op = offsets + (size_t)b * N_SZ * 2 + 2 * biall;
        float ax = __ldg(&ap[0]), ay = __ldg(&ap[1]);
        float ox = __ldg(&op[0]), oy = __ldg(&op[1]);
        float hu = huber1(ox - (gx - ax)) + huber1(oy - (gy - ay));

        g_ce[b] = ce;
        g_hu[b] = hu;
        __threadfence();          // publish before this CTA signals arrival
    }

    __syncthreads();
    if (t == 0) {
        __threadfence();
        s_arrival = atomicAdd(&g_count, 1u);
    }
    __syncthreads();

    // ---- last CTA: deterministic fixed-order 8192 -> 3 reduction ----
    if (s_arrival == GRID - 1) {
        __threadfence();
        float ce = 0.f, hu = 0.f;
        const float4* ce4 = reinterpret_cast<const float4*>(g_ce);
        const float4* hu4 = reinterpret_cast<const float4*>(g_hu);
#pragma unroll
        for (int k = 0; k < 8; k++) {     // thread t owns [t*32, t*32+32)
            float4 v = ce4[t * 8 + k];
            ce += (v.x + v.y) + (v.z + v.w);
        }
#pragma unroll
        for (int k = 0; k < 8; k++) {
            float4 v = hu4[t * 8 + k];
            hu += (v.x + v.y) + (v.z + v.w);
        }
        ce = warp_sum(ce);
        hu = warp_sum(hu);
        if (lane == 0) { s1[warp] = ce; s2[warp] = hu; }
        __syncthreads();
        if (t == 0) {
            float cet = s1[0], hut = s2[0];
#pragma unroll
            for (int w = 1; w < NW; w++) { cet += s1[w]; hut += s2[w]; }
            out[0] = cet + hut;
            out[1] = cet;
            out[2] = hut;
            g_count = 0;          // reset for next graph replay
        }
    }
}

extern "C" void kernel_launch(void* const* d_in, const int* in_sizes, int n_in,
                              void* d_out, int out_size)
{
    const float* anchors = (const float*)d_in[0];
    const float* offsets = (const float*)d_in[1];
    const float* conf    = (const float*)d_in[2];
    const float* gt      = (const float*)d_in[3];
    float* out = (float*)d_out;

    fused_kernel<<<GRID, NT>>>(anchors, offsets, conf, gt, out);
}